// round 14
// baseline (speedup 1.0000x reference)
#include <cuda_runtime.h>
#include <cuda_bf16.h>
#include <cfloat>

// Problem constants (fixed by the dataset)
#define NN 50000
#define EE 800000
#define ET (EE + NN)        // edges + self-loops
#define HXC 128             // H*C = 2*64
#define HIDD 64
#define OUTD 32

#define SCAN_BLK 256
#define NBLK ((NN + SCAN_BLK - 1) / SCAN_BLK)   // 196
#define HB4 ((EE / 4 + 255) / 256)              // hist blocks (4 edges/thread)
#define SCI (EE / 4 + NN)                       // scatter items (vec4 edges + self-loops)
#define SB4 ((SCI + 255) / 256)                 // scatter blocks
#define AB ((NN + 63) / 64)                     // attdot blocks (64 nodes each)

// -------- scratch (device globals; no allocation allowed) --------
__device__ float g_aggx[NN * HXC];   // per-head weighted x sums [N][h0:64|h1:64]
__device__ float g_asrc[NN * 2];     // per-node per-head attention dots
__device__ float g_adst[NN * 2];
__device__ float g_h[NN * HIDD];     // post-FC hidden (layer-1 output)
__device__ float g_wfold[2][64 * 4]; // per-layer W @ [att_src|att_dst] folds
__device__ int   g_deg[NN];
__device__ int   g_off[NN + 1];
__device__ int   g_cur[NN];
__device__ int   g_csr[ET];

__device__ __forceinline__ float lrelu(float x) {
    return (x >= 0.f) ? x : 0.2f * x;
}

// ================= hist (4 edges/thread, int4) + both attention folds =================
__global__ void histfold_kernel(const int* __restrict__ ei,
                                const float* __restrict__ W0,
                                const float* __restrict__ as0, const float* __restrict__ ad0,
                                const float* __restrict__ W1,
                                const float* __restrict__ as1, const float* __restrict__ ad1) {
    int b = blockIdx.x;
    if (b < 2) {
        const float* W   = b ? W1 : W0;
        const float* as_ = b ? as1 : as0;
        const float* ad_ = b ? ad1 : ad0;
        int t = threadIdx.x;
        int k = t >> 2, j = t & 3;
        int h = j & 1;
        const float* av = (j < 2) ? as_ : ad_;
        float acc = 0.f;
#pragma unroll
        for (int c = 0; c < 64; c++)
            acc += W[k * 128 + h * 64 + c] * av[h * 64 + c];
        g_wfold[b][k * 4 + j] = acc;
    } else {
        int idx = (b - 2) * 256 + threadIdx.x;       // 4 edges each
        if (idx < EE / 4) {
            int4 d4 = ((const int4*)(ei + EE))[idx];
            atomicAdd(&g_deg[d4.x], 1);
            atomicAdd(&g_deg[d4.y], 1);
            atomicAdd(&g_deg[d4.z], 1);
            atomicAdd(&g_deg[d4.w], 1);
        }
    }
}

// ================= single-kernel scan (self-loop folded as deg+1) =================
__global__ void scan_kernel() {
    __shared__ int sh[SCAN_BLK];
    __shared__ int base_sh;
    int t = threadIdx.x;
    int start = blockIdx.x * SCAN_BLK;
    int acc = 0;
    for (int i = t; i < start; i += SCAN_BLK) acc += g_deg[i] + 1;
    sh[t] = acc;
    __syncthreads();
    for (int o = SCAN_BLK / 2; o > 0; o >>= 1) {
        if (t < o) sh[t] += sh[t + o];
        __syncthreads();
    }
    if (t == 0) base_sh = sh[0];
    __syncthreads();
    int base = base_sh;
    __syncthreads();
    int i = start + t;
    int v = (i < NN) ? g_deg[i] + 1 : 0;
    sh[t] = v;
    __syncthreads();
    for (int o = 1; o < SCAN_BLK; o <<= 1) {
        int u = (t >= o) ? sh[t - o] : 0;
        __syncthreads();
        sh[t] += u;
        __syncthreads();
    }
    if (i < NN) {
        int off = base + sh[t] - v;
        g_off[i] = off;
        g_cur[i] = off;
        if (i == NN - 1) g_off[NN] = off + v;
    }
}

// -------- attention dots for 64 nodes from raw features via fold --------
__device__ __forceinline__ void attdot_body(const float* __restrict__ x,
                                            const float* __restrict__ wf,
                                            int bidx) {
    __shared__ float xs[64][65];
    __shared__ float wfs[256];
    int tid = threadIdx.x;   // 128 active
    int n0 = bidx * 64;
    for (int i = tid; i < 64 * 64; i += 128) {
        int r = i >> 6, c = i & 63;
        xs[r][c] = (n0 + r < NN) ? x[(n0 + r) * 64 + c] : 0.f;
    }
    wfs[tid] = wf[tid];
    wfs[tid + 128] = wf[tid + 128];
    __syncthreads();
    int r = tid >> 1, which = tid & 1;
    float o0 = 0.f, o1 = 0.f;
#pragma unroll
    for (int k = 0; k < 64; k++) {
        float xv = xs[r][k];
        o0 += xv * wfs[k * 4 + which * 2 + 0];
        o1 += xv * wfs[k * 4 + which * 2 + 1];
    }
    int n = n0 + r;
    if (n < NN) {
        if (which == 0) ((float2*)g_asrc)[n] = make_float2(o0, o1);
        else            ((float2*)g_adst)[n] = make_float2(o0, o1);
    }
}

// ================= scatter (vec4) + layer-1 attention dots (merged) =================
__global__ void scatatt_kernel(const int* __restrict__ ei, const float* __restrict__ x) {
    if (blockIdx.x < AB) {
        if (threadIdx.x >= 128) return;   // exited threads excluded from barriers
        attdot_body(x, g_wfold[0], blockIdx.x);
    } else {
        int idx = (blockIdx.x - AB) * 256 + threadIdx.x;
        if (idx < EE / 4) {
            int4 s4 = ((const int4*)ei)[idx];
            int4 d4 = ((const int4*)(ei + EE))[idx];
            g_csr[atomicAdd(&g_cur[d4.x], 1)] = s4.x;
            g_csr[atomicAdd(&g_cur[d4.y], 1)] = s4.y;
            g_csr[atomicAdd(&g_cur[d4.z], 1)] = s4.z;
            g_csr[atomicAdd(&g_cur[d4.w], 1)] = s4.w;
        } else if (idx < SCI) {
            int n = idx - EE / 4;        // self-loop
            g_csr[atomicAdd(&g_cur[n], 1)] = n;
        }
    }
}

// ================= agg: softmax + raw-x gather (HALF-WARP per dst, x4 unroll) =================
// R12-proven form; __launch_bounds__ pushes occupancy to 6 blocks/SM (48 warps).
__global__ void __launch_bounds__(256, 6) agg_kernel(const float* __restrict__ xin) {
    int tid = blockIdx.x * blockDim.x + threadIdx.x;
    int n = tid >> 4;                 // half-warp id = node
    int sub = threadIdx.x & 15;       // lane within half-warp
    unsigned hmask = 0xFFFFu << (threadIdx.x & 16);
    if (n >= NN) return;
    int o0 = g_off[n], o1 = g_off[n + 1];
    float2 ad = ((const float2*)g_adst)[n];
    float4 a0 = make_float4(0.f, 0.f, 0.f, 0.f);
    float4 a1 = make_float4(0.f, 0.f, 0.f, 0.f);
    float dw0 = 0.f, dw1 = 0.f;
    const float4* x4 = (const float4*)xin;

    for (int base = o0; base < o1; base += 16) {
        int c = min(16, o1 - base);
        int s_l = 0;
        float w0_l = 0.f, w1_l = 0.f;
        if (sub < c) {
            s_l = g_csr[base + sub];
            float2 as = ((const float2*)g_asrc)[s_l];
            w0_l = expf(lrelu(as.x + ad.x));
            w1_l = expf(lrelu(as.y + ad.y));
            dw0 += w0_l; dw1 += w1_l;
        }
        int nIter = (c + 3) & ~3;        // padded lanes: w=0, s=0 (safe)
        for (int j = 0; j < nIter; j += 4) {
            int   s[4];
            float w0[4], w1[4];
#pragma unroll
            for (int u = 0; u < 4; u++) {
                s[u]  = __shfl_sync(hmask, s_l, j + u, 16);
                w0[u] = __shfl_sync(hmask, w0_l, j + u, 16);
                w1[u] = __shfl_sync(hmask, w1_l, j + u, 16);
            }
            float4 v[4];
#pragma unroll
            for (int u = 0; u < 4; u++) v[u] = x4[s[u] * 16 + sub];
#pragma unroll
            for (int u = 0; u < 4; u++) {
                a0.x += w0[u] * v[u].x; a0.y += w0[u] * v[u].y;
                a0.z += w0[u] * v[u].z; a0.w += w0[u] * v[u].w;
                a1.x += w1[u] * v[u].x; a1.y += w1[u] * v[u].y;
                a1.z += w1[u] * v[u].z; a1.w += w1[u] * v[u].w;
            }
        }
    }
#pragma unroll
    for (int o = 8; o > 0; o >>= 1) {
        dw0 += __shfl_xor_sync(hmask, dw0, o, 16);
        dw1 += __shfl_xor_sync(hmask, dw1, o, 16);
    }
    float i0 = 1.f / (dw0 + 1e-16f);
    float i1 = 1.f / (dw1 + 1e-16f);
    float4* out4 = (float4*)g_aggx;
    out4[n * 32 + sub]      = make_float4(a0.x * i0, a0.y * i0, a0.z * i0, a0.w * i0);
    out4[n * 32 + 16 + sub] = make_float4(a1.x * i1, a1.y * i1, a1.z * i1, a1.w * i1);
}

// ================= postW (layer 1): xl = aggx @ W (per head); elu(+bias); @fcw+fcb -> g_h
//                   tail: layer-2 attention dots from the h tile (wfold[1]) =================
__global__ void postW_kernel(const float* __restrict__ W,
                             const float* __restrict__ bias,
                             const float* __restrict__ fcw,
                             const float* __restrict__ fcb) {
    __shared__ float ax[32 * 128];    // 16 KB: aggx tile; later reused for h rows [32*64]
    __shared__ float xl[32][128];     // 16 KB
    __shared__ float part[32][64];    // 8 KB
    __shared__ float wfs[256];
    int tid = threadIdx.x;            // 128
    int n0 = blockIdx.x * 32;
    wfs[tid] = g_wfold[1][tid];
    wfs[tid + 128] = g_wfold[1][tid + 128];
    for (int i = tid; i < 32 * 128; i += 128) {
        int r = i >> 7, c = i & 127;
        ax[r * 128 + c] = (n0 + r < NN) ? g_aggx[(n0 + r) * HXC + c] : 0.f;
    }
    __syncthreads();
    // ---- phase A: xl[r][col] = elu( sum_k ax[r][h*64+k]*W[k][col] + bias[col] ) ----
    {
        int col = tid, h = col >> 6;
        float wA[64];
#pragma unroll
        for (int k = 0; k < 64; k++) wA[k] = W[k * 128 + col];
        float bcol = bias[col];
        for (int ch = 0; ch < 2; ch++) {
            float acc[16];
#pragma unroll
            for (int i = 0; i < 16; i++) acc[i] = 0.f;
#pragma unroll
            for (int i = 0; i < 16; i++) {
                const float4* ar = (const float4*)&ax[(ch * 16 + i) * 128 + h * 64];
#pragma unroll
                for (int k4 = 0; k4 < 16; k4++) {
                    float4 v = ar[k4];
                    acc[i] += v.x * wA[k4 * 4] + v.y * wA[k4 * 4 + 1]
                            + v.z * wA[k4 * 4 + 2] + v.w * wA[k4 * 4 + 3];
                }
            }
#pragma unroll
            for (int i = 0; i < 16; i++) {
                float v = acc[i] + bcol;
                xl[ch * 16 + i][col] = (v > 0.f) ? v : expm1f(v);
            }
        }
    }
    __syncthreads();
    // ---- phase B: h = xl @ fcw + fcb (k split 2 ways over 128 threads) ----
    {
        int col = tid & 63, kh = tid >> 6;
        float fw[64];
#pragma unroll
        for (int k = 0; k < 64; k++) fw[k] = fcw[(kh * 64 + k) * 64 + col];
        float b = fcb[col];
        for (int ch = 0; ch < 4; ch++) {
            float acc[8];
#pragma unroll
            for (int j = 0; j < 8; j++) acc[j] = 0.f;
#pragma unroll
            for (int j = 0; j < 8; j++) {
                const float4* tr = (const float4*)&xl[ch * 8 + j][kh * 64];
#pragma unroll
                for (int k4 = 0; k4 < 16; k4++) {
                    float4 v = tr[k4];
                    acc[j] += v.x * fw[k4 * 4] + v.y * fw[k4 * 4 + 1]
                            + v.z * fw[k4 * 4 + 2] + v.w * fw[k4 * 4 + 3];
                }
            }
            if (kh == 1) {
#pragma unroll
                for (int j = 0; j < 8; j++) part[ch * 8 + j][col] = acc[j];
            }
            __syncthreads();
            if (kh == 0) {
#pragma unroll
                for (int j = 0; j < 8; j++) {
                    int r = ch * 8 + j;
                    float hv = acc[j] + part[r][col] + b;
                    ax[r * 64 + col] = hv;                 // h tile (ax reused)
                    int n = n0 + r;
                    if (n < NN) g_h[n * HIDD + col] = hv;
                }
            }
            __syncthreads();
        }
    }
    // ---- tail: layer-2 attention dots from h tile ----
    {
        int r = tid >> 2, j = tid & 3;   // 32 nodes x 4 outputs
        float o = 0.f;
#pragma unroll
        for (int k = 0; k < 64; k++) o += ax[r * 64 + k] * wfs[k * 4 + j];
        int n = n0 + r;
        if (n < NN) {
            if (j == 0) g_asrc[n * 2 + 0] = o;
            else if (j == 1) g_asrc[n * 2 + 1] = o;
            else if (j == 2) g_adst[n * 2 + 0] = o;
            else             g_adst[n * 2 + 1] = o;
        }
    }
}

// ================= postWfinal (layer 2): + logits + gumbel softmax =================
__global__ void postWfinal_kernel(const float* __restrict__ W,
                                  const float* __restrict__ bias,
                                  const float* __restrict__ fcw,
                                  const float* __restrict__ fcb,
                                  const float* __restrict__ ow,
                                  const float* __restrict__ ob,
                                  const float* __restrict__ gu,
                                  float* __restrict__ out) {
    __shared__ float ax[32 * 128];    // 16 KB; reused for h rows
    __shared__ float xl[32][128];     // 16 KB
    __shared__ float part[32][64];    // 8 KB
    __shared__ float ows[64 * 32];    // 8 KB
    int tid = threadIdx.x;            // 128
    int n0 = blockIdx.x * 32;
    for (int i = tid; i < 64 * 32; i += 128) ows[i] = ow[i];
    for (int i = tid; i < 32 * 128; i += 128) {
        int r = i >> 7, c = i & 127;
        ax[r * 128 + c] = (n0 + r < NN) ? g_aggx[(n0 + r) * HXC + c] : 0.f;
    }
    __syncthreads();
    {
        int col = tid, h = col >> 6;
        float wA[64];
#pragma unroll
        for (int k = 0; k < 64; k++) wA[k] = W[k * 128 + col];
        float bcol = bias[col];
        for (int ch = 0; ch < 2; ch++) {
            float acc[16];
#pragma unroll
            for (int i = 0; i < 16; i++) acc[i] = 0.f;
#pragma unroll
            for (int i = 0; i < 16; i++) {
                const float4* ar = (const float4*)&ax[(ch * 16 + i) * 128 + h * 64];
#pragma unroll
                for (int k4 = 0; k4 < 16; k4++) {
                    float4 v = ar[k4];
                    acc[i] += v.x * wA[k4 * 4] + v.y * wA[k4 * 4 + 1]
                            + v.z * wA[k4 * 4 + 2] + v.w * wA[k4 * 4 + 3];
                }
            }
#pragma unroll
            for (int i = 0; i < 16; i++) {
                float v = acc[i] + bcol;
                xl[ch * 16 + i][col] = (v > 0.f) ? v : expm1f(v);
            }
        }
    }
    __syncthreads();
    {
        int col = tid & 63, kh = tid >> 6;
        float fw[64];
#pragma unroll
        for (int k = 0; k < 64; k++) fw[k] = fcw[(kh * 64 + k) * 64 + col];
        float b = fcb[col];
        for (int ch = 0; ch < 4; ch++) {
            float acc[8];
#pragma unroll
            for (int j = 0; j < 8; j++) acc[j] = 0.f;
#pragma unroll
            for (int j = 0; j < 8; j++) {
                const float4* tr = (const float4*)&xl[ch * 8 + j][kh * 64];
#pragma unroll
                for (int k4 = 0; k4 < 16; k4++) {
                    float4 v = tr[k4];
                    acc[j] += v.x * fw[k4 * 4] + v.y * fw[k4 * 4 + 1]
                            + v.z * fw[k4 * 4 + 2] + v.w * fw[k4 * 4 + 3];
                }
            }
            if (kh == 1) {
#pragma unroll
                for (int j = 0; j < 8; j++) part[ch * 8 + j][col] = acc[j];
            }
            __syncthreads();
            if (kh == 0) {
#pragma unroll
                for (int j = 0; j < 8; j++) {
                    int r = ch * 8 + j;
                    ax[r * 64 + col] = acc[j] + part[r][col] + b;   // h tile
                }
            }
            __syncthreads();
        }
    }
    // ---- head: thread -> node n=tid>>2, cols g4*8..g4*8+7 ----
    int n = tid >> 2, g4 = tid & 3;
    int gn = n0 + n;
    float lg[8];
#pragma unroll
    for (int q = 0; q < 8; q++) lg[q] = ob[g4 * 8 + q];
#pragma unroll
    for (int k = 0; k < 64; k++) {
        float hv = ax[n * 64 + k];
#pragma unroll
        for (int q = 0; q < 8; q++) lg[q] += hv * ows[k * 32 + g4 * 8 + q];
    }
    if (gn < NN) {
        float z[8];
        float m = -FLT_MAX;
#pragma unroll
        for (int q = 0; q < 8; q++) {
            float u = gu[gn * OUTD + g4 * 8 + q];
            float gg = -logf(-logf(u + 1e-20f) + 1e-20f);
            z[q] = lg[q] + gg;
            m = fmaxf(m, z[q]);
        }
        m = fmaxf(m, __shfl_xor_sync(0xffffffffu, m, 1, 4));
        m = fmaxf(m, __shfl_xor_sync(0xffffffffu, m, 2, 4));
        float ssum = 0.f;
        float e[8];
#pragma unroll
        for (int q = 0; q < 8; q++) { e[q] = expf(z[q] - m); ssum += e[q]; }
        ssum += __shfl_xor_sync(0xffffffffu, ssum, 1, 4);
        ssum += __shfl_xor_sync(0xffffffffu, ssum, 2, 4);
        float inv = 1.f / ssum;
#pragma unroll
        for (int q = 0; q < 8; q++) out[gn * OUTD + g4 * 8 + q] = e[q] * inv;
    }
}

// ================= orchestration =================
extern "C" void kernel_launch(void* const* d_in, const int* in_sizes, int n_in,
                              void* d_out, int out_size) {
    const float* x      = (const float*)d_in[0];
    const int*   ei     = (const int*)d_in[1];
    const float* W0     = (const float*)d_in[2];
    const float* asrc0  = (const float*)d_in[3];
    const float* adst0  = (const float*)d_in[4];
    const float* bias0  = (const float*)d_in[5];
    const float* fcw0   = (const float*)d_in[6];
    const float* fcb0   = (const float*)d_in[7];
    const float* W1     = (const float*)d_in[8];
    const float* asrc1  = (const float*)d_in[9];
    const float* adst1  = (const float*)d_in[10];
    const float* bias1  = (const float*)d_in[11];
    const float* fcw1   = (const float*)d_in[12];
    const float* fcb1   = (const float*)d_in[13];
    const float* out_w  = (const float*)d_in[14];
    const float* out_b  = (const float*)d_in[15];
    const float* gu     = (const float*)d_in[16];
    float* out = (float*)d_out;

    float* hin;
    cudaGetSymbolAddress((void**)&hin, g_h);
    int* degp;
    cudaGetSymbolAddress((void**)&degp, g_deg);

    // 1. zero degree counters
    cudaMemsetAsync(degp, 0, NN * sizeof(int));
    // 2. histogram (4 edges/thread) + both folds
    histfold_kernel<<<HB4 + 2, 256>>>(ei, W0, asrc0, adst0, W1, asrc1, adst1);
    // 3. CSR offsets
    scan_kernel<<<NBLK, SCAN_BLK>>>();
    // 4. scatter (vec4 + self-loops) + layer-1 attention dots (merged)
    scatatt_kernel<<<AB + SB4, 256>>>(ei, x);
    // 5. layer-1 aggregation over raw x (half-warp per node)
    agg_kernel<<<(NN * 16 + 255) / 256, 256>>>(x);
    // 6. layer-1 W-apply + FC (+ layer-2 attention dots fused in tail)
    postW_kernel<<<(NN + 31) / 32, 128>>>(W0, bias0, fcw0, fcb0);
    // 7. layer-2 aggregation over h
    agg_kernel<<<(NN * 16 + 255) / 256, 256>>>(hin);
    // 8. layer-2 W-apply + FC + gumbel softmax head
    postWfinal_kernel<<<(NN + 31) / 32, 128>>>(W1, bias1, fcw1, fcb1, out_w, out_b, gu, out);
}

// round 15
// speedup vs baseline: 1.0626x; 1.0626x over previous
#include <cuda_runtime.h>
#include <cuda_bf16.h>
#include <cfloat>

// Problem constants (fixed by the dataset)
#define NN 50000
#define EE 800000
#define ET (EE + NN)        // edges + self-loops
#define HXC 128             // H*C = 2*64
#define HIDD 64
#define OUTD 32

#define SCAN_BLK 256
#define NBLK ((NN + SCAN_BLK - 1) / SCAN_BLK)   // 196
#define HB4 ((EE / 4 + 255) / 256)              // hist blocks (4 edges/thread)
#define SB ((ET + 255) / 256)                   // scatter blocks
#define AB ((NN + 63) / 64)                     // attdot blocks (64 nodes each)

// -------- scratch (device globals; no allocation allowed) --------
__device__ float g_aggx[NN * HXC];   // per-head weighted x sums [N][h0:64|h1:64]
__device__ float g_asrc[NN * 2];     // per-node per-head attention dots
__device__ float g_adst[NN * 2];
__device__ float g_h[NN * HIDD];     // post-FC hidden (layer-1 output)
__device__ float g_wfold[2][64 * 4]; // per-layer W @ [att_src|att_dst] folds
__device__ int   g_deg[NN];
__device__ int   g_off[NN + 1];
__device__ int   g_cur[NN];
__device__ int   g_csr[ET];

__device__ __forceinline__ float lrelu(float x) {
    return (x >= 0.f) ? x : 0.2f * x;
}

// ================= hist (4 edges/thread, int4) + both attention folds =================
__global__ void histfold_kernel(const int* __restrict__ ei,
                                const float* __restrict__ W0,
                                const float* __restrict__ as0, const float* __restrict__ ad0,
                                const float* __restrict__ W1,
                                const float* __restrict__ as1, const float* __restrict__ ad1) {
    int b = blockIdx.x;
    if (b < 2) {
        const float* W   = b ? W1 : W0;
        const float* as_ = b ? as1 : as0;
        const float* ad_ = b ? ad1 : ad0;
        int t = threadIdx.x;
        int k = t >> 2, j = t & 3;
        int h = j & 1;
        const float* av = (j < 2) ? as_ : ad_;
        float acc = 0.f;
#pragma unroll
        for (int c = 0; c < 64; c++)
            acc += W[k * 128 + h * 64 + c] * av[h * 64 + c];
        g_wfold[b][k * 4 + j] = acc;
    } else {
        int idx = (b - 2) * 256 + threadIdx.x;       // 4 edges each
        if (idx < EE / 4) {
            int4 d4 = ((const int4*)(ei + EE))[idx];
            atomicAdd(&g_deg[d4.x], 1);
            atomicAdd(&g_deg[d4.y], 1);
            atomicAdd(&g_deg[d4.z], 1);
            atomicAdd(&g_deg[d4.w], 1);
        }
    }
}

// ================= single-kernel scan (self-loop folded as deg+1) =================
__global__ void scan_kernel() {
    __shared__ int sh[SCAN_BLK];
    __shared__ int base_sh;
    int t = threadIdx.x;
    int start = blockIdx.x * SCAN_BLK;
    int acc = 0;
    for (int i = t; i < start; i += SCAN_BLK) acc += g_deg[i] + 1;
    sh[t] = acc;
    __syncthreads();
    for (int o = SCAN_BLK / 2; o > 0; o >>= 1) {
        if (t < o) sh[t] += sh[t + o];
        __syncthreads();
    }
    if (t == 0) base_sh = sh[0];
    __syncthreads();
    int base = base_sh;
    __syncthreads();
    int i = start + t;
    int v = (i < NN) ? g_deg[i] + 1 : 0;
    sh[t] = v;
    __syncthreads();
    for (int o = 1; o < SCAN_BLK; o <<= 1) {
        int u = (t >= o) ? sh[t - o] : 0;
        __syncthreads();
        sh[t] += u;
        __syncthreads();
    }
    if (i < NN) {
        int off = base + sh[t] - v;
        g_off[i] = off;
        g_cur[i] = off;
        if (i == NN - 1) g_off[NN] = off + v;
    }
}

// -------- attention dots for 64 nodes from raw features via fold --------
__device__ __forceinline__ void attdot_body(const float* __restrict__ x,
                                            const float* __restrict__ wf,
                                            int bidx) {
    __shared__ float xs[64][65];
    __shared__ float wfs[256];
    int tid = threadIdx.x;   // 128 active
    int n0 = bidx * 64;
    for (int i = tid; i < 64 * 64; i += 128) {
        int r = i >> 6, c = i & 63;
        xs[r][c] = (n0 + r < NN) ? x[(n0 + r) * 64 + c] : 0.f;
    }
    wfs[tid] = wf[tid];
    wfs[tid + 128] = wf[tid + 128];
    __syncthreads();
    int r = tid >> 1, which = tid & 1;
    float o0 = 0.f, o1 = 0.f;
#pragma unroll
    for (int k = 0; k < 64; k++) {
        float xv = xs[r][k];
        o0 += xv * wfs[k * 4 + which * 2 + 0];
        o1 += xv * wfs[k * 4 + which * 2 + 1];
    }
    int n = n0 + r;
    if (n < NN) {
        if (which == 0) ((float2*)g_asrc)[n] = make_float2(o0, o1);
        else            ((float2*)g_adst)[n] = make_float2(o0, o1);
    }
}

// ================= scatter (scalar, R12 form) + layer-1 attention dots =================
__global__ void scatatt_kernel(const int* __restrict__ ei, const float* __restrict__ x) {
    if (blockIdx.x < AB) {
        if (threadIdx.x >= 128) return;   // exited threads excluded from barriers
        attdot_body(x, g_wfold[0], blockIdx.x);
    } else {
        int e = (blockIdx.x - AB) * 256 + threadIdx.x;
        if (e >= ET) return;
        int s, d;
        if (e < EE) { s = ei[e]; d = ei[EE + e]; } else { s = d = e - EE; }
        int pos = atomicAdd(&g_cur[d], 1);
        g_csr[pos] = s;
    }
}

// ================= agg: softmax + raw-x gather (HALF-WARP per dst, x4 unroll) =================
// Proven R12 form; weights via fast __expf (rel_err budget 1e-3 >> MUFU error).
__global__ void agg_kernel(const float* __restrict__ xin) {
    int tid = blockIdx.x * blockDim.x + threadIdx.x;
    int n = tid >> 4;                 // half-warp id = node
    int sub = threadIdx.x & 15;       // lane within half-warp
    unsigned hmask = 0xFFFFu << (threadIdx.x & 16);
    if (n >= NN) return;
    int o0 = g_off[n], o1 = g_off[n + 1];
    float2 ad = ((const float2*)g_adst)[n];
    float4 a0 = make_float4(0.f, 0.f, 0.f, 0.f);
    float4 a1 = make_float4(0.f, 0.f, 0.f, 0.f);
    float dw0 = 0.f, dw1 = 0.f;
    const float4* x4 = (const float4*)xin;

    for (int base = o0; base < o1; base += 16) {
        int c = min(16, o1 - base);
        int s_l = 0;
        float w0_l = 0.f, w1_l = 0.f;
        if (sub < c) {
            s_l = g_csr[base + sub];
            float2 as = ((const float2*)g_asrc)[s_l];
            w0_l = __expf(lrelu(as.x + ad.x));
            w1_l = __expf(lrelu(as.y + ad.y));
            dw0 += w0_l; dw1 += w1_l;
        }
        int nIter = (c + 3) & ~3;        // padded lanes: w=0, s=0 (safe)
        for (int j = 0; j < nIter; j += 4) {
            int   s[4];
            float w0[4], w1[4];
#pragma unroll
            for (int u = 0; u < 4; u++) {
                s[u]  = __shfl_sync(hmask, s_l, j + u, 16);
                w0[u] = __shfl_sync(hmask, w0_l, j + u, 16);
                w1[u] = __shfl_sync(hmask, w1_l, j + u, 16);
            }
            float4 v[4];
#pragma unroll
            for (int u = 0; u < 4; u++) v[u] = x4[s[u] * 16 + sub];
#pragma unroll
            for (int u = 0; u < 4; u++) {
                a0.x += w0[u] * v[u].x; a0.y += w0[u] * v[u].y;
                a0.z += w0[u] * v[u].z; a0.w += w0[u] * v[u].w;
                a1.x += w1[u] * v[u].x; a1.y += w1[u] * v[u].y;
                a1.z += w1[u] * v[u].z; a1.w += w1[u] * v[u].w;
            }
        }
    }
#pragma unroll
    for (int o = 8; o > 0; o >>= 1) {
        dw0 += __shfl_xor_sync(hmask, dw0, o, 16);
        dw1 += __shfl_xor_sync(hmask, dw1, o, 16);
    }
    float i0 = 1.f / (dw0 + 1e-16f);
    float i1 = 1.f / (dw1 + 1e-16f);
    float4* out4 = (float4*)g_aggx;
    out4[n * 32 + sub]      = make_float4(a0.x * i0, a0.y * i0, a0.z * i0, a0.w * i0);
    out4[n * 32 + 16 + sub] = make_float4(a1.x * i1, a1.y * i1, a1.z * i1, a1.w * i1);
}

// ================= postW (layer 1): xl = aggx @ W (per head); elu(+bias); @fcw+fcb -> g_h
//                   tail: layer-2 attention dots from the h tile (wfold[1]) =================
__global__ void postW_kernel(const float* __restrict__ W,
                             const float* __restrict__ bias,
                             const float* __restrict__ fcw,
                             const float* __restrict__ fcb) {
    __shared__ float ax[32 * 128];    // 16 KB: aggx tile; later reused for h rows [32*64]
    __shared__ float xl[32][128];     // 16 KB
    __shared__ float part[32][64];    // 8 KB
    __shared__ float wfs[256];
    int tid = threadIdx.x;            // 128
    int n0 = blockIdx.x * 32;
    wfs[tid] = g_wfold[1][tid];
    wfs[tid + 128] = g_wfold[1][tid + 128];
    for (int i = tid; i < 32 * 128; i += 128) {
        int r = i >> 7, c = i & 127;
        ax[r * 128 + c] = (n0 + r < NN) ? g_aggx[(n0 + r) * HXC + c] : 0.f;
    }
    __syncthreads();
    // ---- phase A: xl[r][col] = elu( sum_k ax[r][h*64+k]*W[k][col] + bias[col] ) ----
    {
        int col = tid, h = col >> 6;
        float wA[64];
#pragma unroll
        for (int k = 0; k < 64; k++) wA[k] = W[k * 128 + col];
        float bcol = bias[col];
        for (int ch = 0; ch < 2; ch++) {
            float acc[16];
#pragma unroll
            for (int i = 0; i < 16; i++) acc[i] = 0.f;
#pragma unroll
            for (int i = 0; i < 16; i++) {
                const float4* ar = (const float4*)&ax[(ch * 16 + i) * 128 + h * 64];
#pragma unroll
                for (int k4 = 0; k4 < 16; k4++) {
                    float4 v = ar[k4];
                    acc[i] += v.x * wA[k4 * 4] + v.y * wA[k4 * 4 + 1]
                            + v.z * wA[k4 * 4 + 2] + v.w * wA[k4 * 4 + 3];
                }
            }
#pragma unroll
            for (int i = 0; i < 16; i++) {
                float v = acc[i] + bcol;
                xl[ch * 16 + i][col] = (v > 0.f) ? v : expm1f(v);
            }
        }
    }
    __syncthreads();
    // ---- phase B: h = xl @ fcw + fcb (k split 2 ways over 128 threads) ----
    {
        int col = tid & 63, kh = tid >> 6;
        float fw[64];
#pragma unroll
        for (int k = 0; k < 64; k++) fw[k] = fcw[(kh * 64 + k) * 64 + col];
        float b = fcb[col];
        for (int ch = 0; ch < 4; ch++) {
            float acc[8];
#pragma unroll
            for (int j = 0; j < 8; j++) acc[j] = 0.f;
#pragma unroll
            for (int j = 0; j < 8; j++) {
                const float4* tr = (const float4*)&xl[ch * 8 + j][kh * 64];
#pragma unroll
                for (int k4 = 0; k4 < 16; k4++) {
                    float4 v = tr[k4];
                    acc[j] += v.x * fw[k4 * 4] + v.y * fw[k4 * 4 + 1]
                            + v.z * fw[k4 * 4 + 2] + v.w * fw[k4 * 4 + 3];
                }
            }
            if (kh == 1) {
#pragma unroll
                for (int j = 0; j < 8; j++) part[ch * 8 + j][col] = acc[j];
            }
            __syncthreads();
            if (kh == 0) {
#pragma unroll
                for (int j = 0; j < 8; j++) {
                    int r = ch * 8 + j;
                    float hv = acc[j] + part[r][col] + b;
                    ax[r * 64 + col] = hv;                 // h tile (ax reused)
                    int n = n0 + r;
                    if (n < NN) g_h[n * HIDD + col] = hv;
                }
            }
            __syncthreads();
        }
    }
    // ---- tail: layer-2 attention dots from h tile ----
    {
        int r = tid >> 2, j = tid & 3;   // 32 nodes x 4 outputs
        float o = 0.f;
#pragma unroll
        for (int k = 0; k < 64; k++) o += ax[r * 64 + k] * wfs[k * 4 + j];
        int n = n0 + r;
        if (n < NN) {
            if (j == 0) g_asrc[n * 2 + 0] = o;
            else if (j == 1) g_asrc[n * 2 + 1] = o;
            else if (j == 2) g_adst[n * 2 + 0] = o;
            else             g_adst[n * 2 + 1] = o;
        }
    }
}

// ================= postWfinal (layer 2): + logits + gumbel softmax =================
__global__ void postWfinal_kernel(const float* __restrict__ W,
                                  const float* __restrict__ bias,
                                  const float* __restrict__ fcw,
                                  const float* __restrict__ fcb,
                                  const float* __restrict__ ow,
                                  const float* __restrict__ ob,
                                  const float* __restrict__ gu,
                                  float* __restrict__ out) {
    __shared__ float ax[32 * 128];    // 16 KB; reused for h rows
    __shared__ float xl[32][128];     // 16 KB
    __shared__ float part[32][64];    // 8 KB
    __shared__ float ows[64 * 32];    // 8 KB
    int tid = threadIdx.x;            // 128
    int n0 = blockIdx.x * 32;
    for (int i = tid; i < 64 * 32; i += 128) ows[i] = ow[i];
    for (int i = tid; i < 32 * 128; i += 128) {
        int r = i >> 7, c = i & 127;
        ax[r * 128 + c] = (n0 + r < NN) ? g_aggx[(n0 + r) * HXC + c] : 0.f;
    }
    __syncthreads();
    {
        int col = tid, h = col >> 6;
        float wA[64];
#pragma unroll
        for (int k = 0; k < 64; k++) wA[k] = W[k * 128 + col];
        float bcol = bias[col];
        for (int ch = 0; ch < 2; ch++) {
            float acc[16];
#pragma unroll
            for (int i = 0; i < 16; i++) acc[i] = 0.f;
#pragma unroll
            for (int i = 0; i < 16; i++) {
                const float4* ar = (const float4*)&ax[(ch * 16 + i) * 128 + h * 64];
#pragma unroll
                for (int k4 = 0; k4 < 16; k4++) {
                    float4 v = ar[k4];
                    acc[i] += v.x * wA[k4 * 4] + v.y * wA[k4 * 4 + 1]
                            + v.z * wA[k4 * 4 + 2] + v.w * wA[k4 * 4 + 3];
                }
            }
#pragma unroll
            for (int i = 0; i < 16; i++) {
                float v = acc[i] + bcol;
                xl[ch * 16 + i][col] = (v > 0.f) ? v : expm1f(v);
            }
        }
    }
    __syncthreads();
    {
        int col = tid & 63, kh = tid >> 6;
        float fw[64];
#pragma unroll
        for (int k = 0; k < 64; k++) fw[k] = fcw[(kh * 64 + k) * 64 + col];
        float b = fcb[col];
        for (int ch = 0; ch < 4; ch++) {
            float acc[8];
#pragma unroll
            for (int j = 0; j < 8; j++) acc[j] = 0.f;
#pragma unroll
            for (int j = 0; j < 8; j++) {
                const float4* tr = (const float4*)&xl[ch * 8 + j][kh * 64];
#pragma unroll
                for (int k4 = 0; k4 < 16; k4++) {
                    float4 v = tr[k4];
                    acc[j] += v.x * fw[k4 * 4] + v.y * fw[k4 * 4 + 1]
                            + v.z * fw[k4 * 4 + 2] + v.w * fw[k4 * 4 + 3];
                }
            }
            if (kh == 1) {
#pragma unroll
                for (int j = 0; j < 8; j++) part[ch * 8 + j][col] = acc[j];
            }
            __syncthreads();
            if (kh == 0) {
#pragma unroll
                for (int j = 0; j < 8; j++) {
                    int r = ch * 8 + j;
                    ax[r * 64 + col] = acc[j] + part[r][col] + b;   // h tile
                }
            }
            __syncthreads();
        }
    }
    // ---- head: thread -> node n=tid>>2, cols g4*8..g4*8+7; fast-math transcendentals ----
    int n = tid >> 2, g4 = tid & 3;
    int gn = n0 + n;
    float lg[8];
#pragma unroll
    for (int q = 0; q < 8; q++) lg[q] = ob[g4 * 8 + q];
#pragma unroll
    for (int k = 0; k < 64; k++) {
        float hv = ax[n * 64 + k];
#pragma unroll
        for (int q = 0; q < 8; q++) lg[q] += hv * ows[k * 32 + g4 * 8 + q];
    }
    if (gn < NN) {
        float z[8];
        float m = -FLT_MAX;
#pragma unroll
        for (int q = 0; q < 8; q++) {
            float u = gu[gn * OUTD + g4 * 8 + q];
            float gg = -__logf(-__logf(u + 1e-20f) + 1e-20f);
            z[q] = lg[q] + gg;
            m = fmaxf(m, z[q]);
        }
        m = fmaxf(m, __shfl_xor_sync(0xffffffffu, m, 1, 4));
        m = fmaxf(m, __shfl_xor_sync(0xffffffffu, m, 2, 4));
        float ssum = 0.f;
        float e[8];
#pragma unroll
        for (int q = 0; q < 8; q++) { e[q] = __expf(z[q] - m); ssum += e[q]; }
        ssum += __shfl_xor_sync(0xffffffffu, ssum, 1, 4);
        ssum += __shfl_xor_sync(0xffffffffu, ssum, 2, 4);
        float inv = 1.f / ssum;
#pragma unroll
        for (int q = 0; q < 8; q++) out[gn * OUTD + g4 * 8 + q] = e[q] * inv;
    }
}

// ================= orchestration =================
extern "C" void kernel_launch(void* const* d_in, const int* in_sizes, int n_in,
                              void* d_out, int out_size) {
    const float* x      = (const float*)d_in[0];
    const int*   ei     = (const int*)d_in[1];
    const float* W0     = (const float*)d_in[2];
    const float* asrc0  = (const float*)d_in[3];
    const float* adst0  = (const float*)d_in[4];
    const float* bias0  = (const float*)d_in[5];
    const float* fcw0   = (const float*)d_in[6];
    const float* fcb0   = (const float*)d_in[7];
    const float* W1     = (const float*)d_in[8];
    const float* asrc1  = (const float*)d_in[9];
    const float* adst1  = (const float*)d_in[10];
    const float* bias1  = (const float*)d_in[11];
    const float* fcw1   = (const float*)d_in[12];
    const float* fcb1   = (const float*)d_in[13];
    const float* out_w  = (const float*)d_in[14];
    const float* out_b  = (const float*)d_in[15];
    const float* gu     = (const float*)d_in[16];
    float* out = (float*)d_out;

    float* hin;
    cudaGetSymbolAddress((void**)&hin, g_h);
    int* degp;
    cudaGetSymbolAddress((void**)&degp, g_deg);

    // 1. zero degree counters
    cudaMemsetAsync(degp, 0, NN * sizeof(int));
    // 2. histogram (4 edges/thread) + both folds
    histfold_kernel<<<HB4 + 2, 256>>>(ei, W0, asrc0, adst0, W1, asrc1, adst1);
    // 3. CSR offsets
    scan_kernel<<<NBLK, SCAN_BLK>>>();
    // 4. scatter (scalar) + layer-1 attention dots (merged)
    scatatt_kernel<<<AB + SB, 256>>>(ei, x);
    // 5. layer-1 aggregation over raw x (half-warp per node)
    agg_kernel<<<(NN * 16 + 255) / 256, 256>>>(x);
    // 6. layer-1 W-apply + FC (+ layer-2 attention dots fused in tail)
    postW_kernel<<<(NN + 31) / 32, 128>>>(W0, bias0, fcw0, fcb0);
    // 7. layer-2 aggregation over h
    agg_kernel<<<(NN * 16 + 255) / 256, 256>>>(hin);
    // 8. layer-2 W-apply + FC + gumbel softmax head
    postWfinal_kernel<<<(NN + 31) / 32, 128>>>(W1, bias1, fcw1, fcb1, out_w, out_b, gu, out);
}